// round 13
// baseline (speedup 1.0000x reference)
#include <cuda_runtime.h>
#include <cuda_fp16.h>

#define NB    50
#define HID   32
#define HALFD 16
#define JJ    16         // HID/2 packed pairs
#define VSTH  17         // u32 stride per bucket row (odd -> <=2-way conflicts)
#define W2ST  17         // padded W2 row stride in smem
#define TPB   256
#define CR    4          // rows per thread, phase-1 chunks
#define CHROWS (TPB * CR)   // 1024 rows per phase-1 chunk
#define NBLK  740        // 148 SMs x 5 blocks, persistent
#define P1PB  2          // phase-1 chunks per block (exactly balanced)

__device__ __forceinline__ unsigned long long pack2(float lo, float hi) {
    unsigned long long r;
    asm("mov.b64 %0, {%1, %2};" : "=l"(r) : "f"(lo), "f"(hi));
    return r;
}
__device__ __forceinline__ unsigned long long fma2(unsigned long long a,
                                                   unsigned long long b,
                                                   unsigned long long c) {
    unsigned long long d;
    asm("fma.rn.f32x2 %0, %1, %2, %3;" : "=l"(d) : "l"(a), "l"(b), "l"(c));
    return d;
}
__device__ __forceinline__ void unpack2(unsigned long long v, float& lo, float& hi) {
    asm("mov.b64 {%0, %1}, %2;" : "=f"(lo), "=f"(hi) : "l"(v));
}

template <int CRN>
__device__ __forceinline__ void process_rows(
    int base, int B,
    const float2* __restrict__ x, const int* __restrict__ buckets,
    const float* sAB, const float* sC, const unsigned* sVh, const float* sc,
    float* __restrict__ out)
{
    unsigned long long x0d[CRN], x1d[CRN];
    float acc0[CRN], acc1[CRN];
    int   va[CRN];

    #pragma unroll
    for (int r = 0; r < CRN; r++) {
        int idx = base + r * TPB;
        bool p = idx < B;
        float2 xv = p ? __ldg(&x[idx]) : make_float2(0.f, 0.f);
        int b = p ? buckets[idx] : 0;
        b = ((unsigned)b < NB) ? b : (NB - 1);
        va[r]   = b * VSTH;
        x0d[r]  = pack2(xv.x, xv.x);
        x1d[r]  = pack2(xv.y, xv.y);
        acc0[r] = sc[b];           // head bias folded into accumulator
        acc1[r] = 0.f;
    }

    #pragma unroll
    for (int jj = 0; jj < JJ; jj++) {
        // warp-uniform weight pairs: broadcast LDS.64 (1 wavefront each)
        unsigned long long a2  = *(const unsigned long long*)&sAB[2 * jj];
        unsigned long long b2w = *(const unsigned long long*)&sAB[HID + 2 * jj];
        unsigned long long c2  = *(const unsigned long long*)&sC[2 * jj];
        #pragma unroll
        for (int r = 0; r < CRN; r++) {
            unsigned long long z = fma2(x1d[r], b2w, c2);
            z = fma2(x0d[r], a2, z);
            float z0, z1;
            unpack2(z, z0, z1);
            float h0 = fmaxf(z0, 0.f);
            float h1 = fmaxf(z1, 0.f);
            unsigned vh = sVh[va[r] + jj];     // one LDS.32 = both fp16 weights
            float2 vf = __half22float2(*reinterpret_cast<const __half2*>(&vh));
            acc0[r] = fmaf(h0, vf.x, acc0[r]);
            acc1[r] = fmaf(h1, vf.y, acc1[r]);
        }
    }

    #pragma unroll
    for (int r = 0; r < CRN; r++) {
        int idx = base + r * TPB;
        if (idx < B) out[idx] = acc0[r] + acc1[r];
    }
}

__global__ __launch_bounds__(TPB, 5)
void lightwin_kernel(const float2* __restrict__ x, const int* __restrict__ buckets,
                     const float* __restrict__ W1, const float* __restrict__ b1,
                     const float* __restrict__ W2, const float* __restrict__ b2v,
                     const float* __restrict__ Wh, const float* __restrict__ bh,
                     float* __restrict__ out, int B, int base2, int n2) {
    __shared__ __align__(16) float sAB[HID * 2];     // W1 row0 | W1 row1
    __shared__ __align__(16) float sC[HID];          // b1
    __shared__ unsigned sVh[NB * VSTH];              // V = Wh @ W2^T, half2 pairs
    __shared__ float sc[NB];                         // c[b] = bh[b] + b2 . Wh[b]
    // staging for fused precompute (coalesced loads; bank-aware strides)
    __shared__ float sW2[HID * W2ST];
    __shared__ float sWh[NB * HALFD];
    __shared__ float sB2[HALFD];
    __shared__ float sBh[NB];

    int tid = threadIdx.x;

    // ---- stage 1: coalesced global -> smem (once per persistent block)
    if (tid < HID * 2)     sAB[tid] = W1[tid];
    if (tid < HID)         sC[tid]  = b1[tid];
    for (int i = tid; i < HID * HALFD; i += TPB)
        sW2[(i >> 4) * W2ST + (i & 15)] = W2[i];
    for (int i = tid; i < NB * HALFD; i += TPB)
        sWh[i] = Wh[i];
    if (tid < HALFD)       sB2[tid] = b2v[tid];
    if (tid < NB)          sBh[tid] = bh[tid];
    __syncthreads();

    // ---- stage 2: combined head weights V (half2) + folded bias c
    for (int e = tid; e < NB * JJ; e += TPB) {
        int b = e >> 4, jj = e & 15;
        const float* whp = &sWh[b * HALFD];
        const float* wa  = &sW2[(2 * jj)     * W2ST];
        const float* wb  = &sW2[(2 * jj + 1) * W2ST];
        float s0 = 0.f, s1 = 0.f;
        #pragma unroll
        for (int k = 0; k < HALFD; k++) {
            float wh = whp[k];
            s0 = fmaf(wa[k], wh, s0);
            s1 = fmaf(wb[k], wh, s1);
        }
        __half2 h = __floats2half2_rn(s0, s1);
        sVh[b * VSTH + jj] = *reinterpret_cast<unsigned*>(&h);
    }
    for (int b = tid; b < NB; b += TPB) {
        float s = sBh[b];
        #pragma unroll
        for (int k = 0; k < HALFD; k++)
            s = fmaf(sB2[k], sWh[b * HALFD + k], s);
        sc[b] = s;
    }
    __syncthreads();

    // ---- phase 1: exactly P1PB big chunks per block (perfect balance)
    #pragma unroll 1
    for (int k = 0; k < P1PB; k++) {
        int base = (blockIdx.x * P1PB + k) * CHROWS + tid;
        process_rows<CR>(base, B, x, buckets, sAB, sC, sVh, sc, out);
    }

    // ---- phase 2: fine 256-row chunks, round-robin (max 4% residual tail)
    #pragma unroll 1
    for (int c2 = blockIdx.x; c2 < n2; c2 += NBLK) {
        int base = base2 + c2 * TPB + tid;
        process_rows<1>(base, B, x, buckets, sAB, sC, sVh, sc, out);
    }
}

extern "C" void kernel_launch(void* const* d_in, const int* in_sizes, int n_in,
                              void* d_out, int out_size) {
    const float2* x     = (const float2*)d_in[0];
    const int* buckets  = (const int*)d_in[1];
    const float* W1     = (const float*)d_in[2];
    const float* b1     = (const float*)d_in[3];
    const float* W2     = (const float*)d_in[4];
    const float* b2v    = (const float*)d_in[5];
    const float* Wh     = (const float*)d_in[6];
    const float* bh     = (const float*)d_in[7];
    float* out          = (float*)d_out;

    int B = in_sizes[1];  // buckets element count = row count

    long long covered = (long long)NBLK * P1PB * CHROWS;   // 1,515,520
    int base2, n2;
    if (covered >= B) { base2 = B; n2 = 0; }
    else {
        base2 = (int)covered;
        n2 = (B - base2 + TPB - 1) / TPB;                  // 1893 fine chunks
    }
    lightwin_kernel<<<NBLK, TPB>>>(x, buckets, W1, b1, W2, b2v, Wh, bh,
                                   out, B, base2, n2);
}

// round 14
// speedup vs baseline: 2.0468x; 2.0468x over previous
#include <cuda_runtime.h>
#include <cuda_fp16.h>

#define NB    50
#define HID   32
#define HALFD 16
#define JJ    16         // HID/2 packed pairs
#define VSTH  17         // u32 stride per bucket row (odd -> <=2-way conflicts)
#define W2ST  17         // padded W2 row stride in smem
#define TPB   256
#define CR    4          // rows per thread, full tiles
#define TILE  (TPB * CR)    // 1024 rows per full tile
#define NBLK  740        // 148 SMs x 5 blocks, persistent

__device__ __forceinline__ unsigned long long pack2(float lo, float hi) {
    unsigned long long r;
    asm("mov.b64 %0, {%1, %2};" : "=l"(r) : "f"(lo), "f"(hi));
    return r;
}
__device__ __forceinline__ unsigned long long fma2(unsigned long long a,
                                                   unsigned long long b,
                                                   unsigned long long c) {
    unsigned long long d;
    asm("fma.rn.f32x2 %0, %1, %2, %3;" : "=l"(d) : "l"(a), "l"(b), "l"(c));
    return d;
}
__device__ __forceinline__ void unpack2(unsigned long long v, float& lo, float& hi) {
    asm("mov.b64 {%0, %1}, %2;" : "=f"(lo), "=f"(hi) : "l"(v));
}

__global__ __launch_bounds__(TPB, 5)
void lightwin_kernel(const float2* __restrict__ x, const int* __restrict__ buckets,
                     const float* __restrict__ W1, const float* __restrict__ b1,
                     const float* __restrict__ W2, const float* __restrict__ b2v,
                     const float* __restrict__ Wh, const float* __restrict__ bh,
                     float* __restrict__ out, int B) {
    __shared__ __align__(16) float sAB[HID * 2];     // W1 row0 | W1 row1
    __shared__ __align__(16) float sC[HID];          // b1
    __shared__ unsigned sVh[NB * VSTH];              // V = Wh @ W2^T, half2 pairs
    __shared__ float sc[NB];                         // c[b] = bh[b] + b2 . Wh[b]
    // staging for fused precompute (coalesced loads; bank-aware strides)
    __shared__ float sW2[HID * W2ST];
    __shared__ float sWh[NB * HALFD];
    __shared__ float sB2[HALFD];
    __shared__ float sBh[NB];

    int tid = threadIdx.x;

    // ---- stage 1: coalesced global -> smem (once per persistent block)
    if (tid < HID * 2)     sAB[tid] = W1[tid];
    if (tid < HID)         sC[tid]  = b1[tid];
    for (int i = tid; i < HID * HALFD; i += TPB)
        sW2[(i >> 4) * W2ST + (i & 15)] = W2[i];
    for (int i = tid; i < NB * HALFD; i += TPB)
        sWh[i] = Wh[i];
    if (tid < HALFD)       sB2[tid] = b2v[tid];
    if (tid < NB)          sBh[tid] = bh[tid];
    __syncthreads();

    // ---- stage 2: combined head weights V (half2) + folded bias c
    for (int e = tid; e < NB * JJ; e += TPB) {
        int b = e >> 4, jj = e & 15;
        const float* whp = &sWh[b * HALFD];
        const float* wa  = &sW2[(2 * jj)     * W2ST];
        const float* wb  = &sW2[(2 * jj + 1) * W2ST];
        float s0 = 0.f, s1 = 0.f;
        #pragma unroll
        for (int k = 0; k < HALFD; k++) {
            float wh = whp[k];
            s0 = fmaf(wa[k], wh, s0);
            s1 = fmaf(wb[k], wh, s1);
        }
        __half2 h = __floats2half2_rn(s0, s1);
        sVh[b * VSTH + jj] = *reinterpret_cast<unsigned*>(&h);
    }
    for (int b = tid; b < NB; b += TPB) {
        float s = sBh[b];
        #pragma unroll
        for (int k = 0; k < HALFD; k++)
            s = fmaf(sB2[k], sWh[b * HALFD + k], s);
        sc[b] = s;
    }
    __syncthreads();

    // ---- balanced per-block row range: imbalance <= 1 row
    int start = (int)(((long long)blockIdx.x       * B) / NBLK);
    int end   = (int)(((long long)(blockIdx.x + 1) * B) / NBLK);
    int nfull = (end - start) / TILE;

    // ---- full CR=4 tiles: provably in-range -> NO bounds predicates
    #pragma unroll 1
    for (int k = 0; k < nfull; k++) {
        int base = start + k * TILE + tid;

        unsigned long long x0d[CR], x1d[CR];
        float acc0[CR], acc1[CR];
        int   va[CR];

        #pragma unroll
        for (int r = 0; r < CR; r++) {
            int idx = base + r * TPB;
            float2 xv = __ldg(&x[idx]);
            int b = buckets[idx];
            b = ((unsigned)b < NB) ? b : (NB - 1);
            va[r]   = b * VSTH;
            x0d[r]  = pack2(xv.x, xv.x);
            x1d[r]  = pack2(xv.y, xv.y);
            acc0[r] = sc[b];           // head bias folded into accumulator
            acc1[r] = 0.f;
        }

        #pragma unroll
        for (int jj = 0; jj < JJ; jj++) {
            unsigned long long a2  = *(const unsigned long long*)&sAB[2 * jj];
            unsigned long long b2w = *(const unsigned long long*)&sAB[HID + 2 * jj];
            unsigned long long c2  = *(const unsigned long long*)&sC[2 * jj];
            #pragma unroll
            for (int r = 0; r < CR; r++) {
                unsigned long long z = fma2(x1d[r], b2w, c2);
                z = fma2(x0d[r], a2, z);
                float z0, z1;
                unpack2(z, z0, z1);
                float h0 = fmaxf(z0, 0.f);
                float h1 = fmaxf(z1, 0.f);
                unsigned vh = sVh[va[r] + jj];     // one LDS.32 = both fp16 weights
                float2 vf = __half22float2(*reinterpret_cast<__half2*>(&vh));
                acc0[r] = fmaf(h0, vf.x, acc0[r]);
                acc1[r] = fmaf(h1, vf.y, acc1[r]);
            }
        }

        #pragma unroll
        for (int r = 0; r < CR; r++)
            out[base + r * TPB] = acc0[r] + acc1[r];
    }

    // ---- tail: <=3 fine 256-row steps, predicated (inline, direct smem)
    #pragma unroll 1
    for (int b0 = start + nfull * TILE; b0 < end; b0 += TPB) {
        int idx = b0 + tid;
        bool p = idx < end;
        float2 xv = p ? __ldg(&x[idx]) : make_float2(0.f, 0.f);
        int b = p ? buckets[idx] : 0;
        b = ((unsigned)b < NB) ? b : (NB - 1);
        int vat = b * VSTH;
        unsigned long long x0 = pack2(xv.x, xv.x);
        unsigned long long x1 = pack2(xv.y, xv.y);
        float a0 = sc[b], a1 = 0.f;

        #pragma unroll
        for (int jj = 0; jj < JJ; jj++) {
            unsigned long long a2  = *(const unsigned long long*)&sAB[2 * jj];
            unsigned long long b2w = *(const unsigned long long*)&sAB[HID + 2 * jj];
            unsigned long long c2  = *(const unsigned long long*)&sC[2 * jj];
            unsigned long long z = fma2(x1, b2w, c2);
            z = fma2(x0, a2, z);
            float z0, z1;
            unpack2(z, z0, z1);
            float h0 = fmaxf(z0, 0.f);
            float h1 = fmaxf(z1, 0.f);
            unsigned vh = sVh[vat + jj];
            float2 vf = __half22float2(*reinterpret_cast<__half2*>(&vh));
            a0 = fmaf(h0, vf.x, a0);
            a1 = fmaf(h1, vf.y, a1);
        }
        if (p) out[idx] = a0 + a1;
    }
}

extern "C" void kernel_launch(void* const* d_in, const int* in_sizes, int n_in,
                              void* d_out, int out_size) {
    const float2* x     = (const float2*)d_in[0];
    const int* buckets  = (const int*)d_in[1];
    const float* W1     = (const float*)d_in[2];
    const float* b1     = (const float*)d_in[3];
    const float* W2     = (const float*)d_in[4];
    const float* b2v    = (const float*)d_in[5];
    const float* Wh     = (const float*)d_in[6];
    const float* bh     = (const float*)d_in[7];
    float* out          = (float*)d_out;

    int B = in_sizes[1];  // buckets element count = row count

    lightwin_kernel<<<NBLK, TPB>>>(x, buckets, W1, b1, W2, b2v, Wh, bh, out, B);
}

// round 15
// speedup vs baseline: 2.0667x; 1.0097x over previous
#include <cuda_runtime.h>
#include <cuda_fp16.h>

#define NB    50
#define HID   32
#define HALFD 16
#define JJ    16         // HID/2 packed pairs
#define VSTH  17         // u32 stride per bucket row (odd -> <=2-way conflicts)
#define W2ST  17         // padded W2 row stride in smem
#define TPB   256
#define CR    4          // rows per thread, full tiles
#define TILE  (TPB * CR)    // 1024 rows per full tile
#define NBLK  740        // 148 SMs x 5 blocks, persistent

__device__ __forceinline__ unsigned long long pack2(float lo, float hi) {
    unsigned long long r;
    asm("mov.b64 %0, {%1, %2};" : "=l"(r) : "f"(lo), "f"(hi));
    return r;
}
__device__ __forceinline__ unsigned long long fma2(unsigned long long a,
                                                   unsigned long long b,
                                                   unsigned long long c) {
    unsigned long long d;
    asm("fma.rn.f32x2 %0, %1, %2, %3;" : "=l"(d) : "l"(a), "l"(b), "l"(c));
    return d;
}
__device__ __forceinline__ void unpack2(unsigned long long v, float& lo, float& hi) {
    asm("mov.b64 {%0, %1}, %2;" : "=f"(lo), "=f"(hi) : "l"(v));
}

__global__ __launch_bounds__(TPB, 5)
void lightwin_kernel(const float2* __restrict__ x, const int* __restrict__ buckets,
                     const float* __restrict__ W1, const float* __restrict__ b1,
                     const float* __restrict__ W2, const float* __restrict__ b2v,
                     const float* __restrict__ Wh, const float* __restrict__ bh,
                     float* __restrict__ out, int B) {
    __shared__ __align__(16) float sAB[HID * 2];     // W1 row0 | W1 row1
    __shared__ __align__(16) float sC[HID];          // b1
    __shared__ unsigned sVh[NB * VSTH];              // V = Wh @ W2^T, half2 pairs
    __shared__ float sc[NB];                         // c[b] = bh[b] + b2 . Wh[b]
    // staging for fused precompute (coalesced loads; bank-aware strides)
    __shared__ float sW2[HID * W2ST];
    __shared__ float sWh[NB * HALFD];
    __shared__ float sB2[HALFD];
    __shared__ float sBh[NB];

    int tid = threadIdx.x;

    // ---- stage 1: coalesced global -> smem (once per persistent block)
    if (tid < HID * 2)     sAB[tid] = W1[tid];
    if (tid < HID)         sC[tid]  = b1[tid];
    for (int i = tid; i < HID * HALFD; i += TPB)
        sW2[(i >> 4) * W2ST + (i & 15)] = W2[i];
    for (int i = tid; i < NB * HALFD; i += TPB)
        sWh[i] = Wh[i];
    if (tid < HALFD)       sB2[tid] = b2v[tid];
    if (tid < NB)          sBh[tid] = bh[tid];
    __syncthreads();

    // ---- stage 2: combined head weights V (half2) + folded bias c
    for (int e = tid; e < NB * JJ; e += TPB) {
        int b = e >> 4, jj = e & 15;
        const float* whp = &sWh[b * HALFD];
        const float* wa  = &sW2[(2 * jj)     * W2ST];
        const float* wb  = &sW2[(2 * jj + 1) * W2ST];
        float s0 = 0.f, s1 = 0.f;
        #pragma unroll
        for (int k = 0; k < HALFD; k++) {
            float wh = whp[k];
            s0 = fmaf(wa[k], wh, s0);
            s1 = fmaf(wb[k], wh, s1);
        }
        __half2 h = __floats2half2_rn(s0, s1);
        sVh[b * VSTH + jj] = *reinterpret_cast<unsigned*>(&h);
    }
    for (int b = tid; b < NB; b += TPB) {
        float s = sBh[b];
        #pragma unroll
        for (int k = 0; k < HALFD; k++)
            s = fmaf(sB2[k], sWh[b * HALFD + k], s);
        sc[b] = s;
    }
    __syncthreads();

    // ---- balanced, 256-ALIGNED per-block row range (sizes 2560 or 2816)
    long long t0 = (long long)blockIdx.x       * B / NBLK;
    long long t1 = (long long)(blockIdx.x + 1) * B / NBLK;
    int start = (int)(t0 & ~255LL);
    int end   = (blockIdx.x == NBLK - 1) ? B : (int)(t1 & ~255LL);
    int nfull = (end - start) / TILE;

    // ---- full CR=4 tiles: aligned and provably in-range -> no predicates
    #pragma unroll 1
    for (int k = 0; k < nfull; k++) {
        int base = start + k * TILE + tid;

        unsigned long long x0d[CR], x1d[CR];
        float acc0[CR], acc1[CR];
        int   va[CR];

        #pragma unroll
        for (int r = 0; r < CR; r++) {
            int idx = base + r * TPB;
            float2 xv = __ldg(&x[idx]);
            int b = buckets[idx];
            b = ((unsigned)b < NB) ? b : (NB - 1);
            va[r]   = b * VSTH;
            x0d[r]  = pack2(xv.x, xv.x);
            x1d[r]  = pack2(xv.y, xv.y);
            acc0[r] = sc[b];           // head bias folded into accumulator
            acc1[r] = 0.f;
        }

        #pragma unroll
        for (int jj = 0; jj < JJ; jj++) {
            unsigned long long a2  = *(const unsigned long long*)&sAB[2 * jj];
            unsigned long long b2w = *(const unsigned long long*)&sAB[HID + 2 * jj];
            unsigned long long c2  = *(const unsigned long long*)&sC[2 * jj];
            #pragma unroll
            for (int r = 0; r < CR; r++) {
                unsigned long long z = fma2(x1d[r], b2w, c2);
                z = fma2(x0d[r], a2, z);
                float z0, z1;
                unpack2(z, z0, z1);
                float h0 = fmaxf(z0, 0.f);
                float h1 = fmaxf(z1, 0.f);
                unsigned vh = sVh[va[r] + jj];     // one LDS.32 = both fp16 weights
                float2 vf = __half22float2(*reinterpret_cast<__half2*>(&vh));
                acc0[r] = fmaf(h0, vf.x, acc0[r]);
                acc1[r] = fmaf(h1, vf.y, acc1[r]);
            }
        }

        #pragma unroll
        for (int r = 0; r < CR; r++)
            out[base + r * TPB] = acc0[r] + acc1[r];
    }

    // ---- tail: <=3 aligned 256-row steps (predicate uniformly true except
    //      the final 128-row sliver of the last block)
    #pragma unroll 1
    for (int b0 = start + nfull * TILE; b0 < end; b0 += TPB) {
        int idx = b0 + tid;
        bool p = idx < end;
        float2 xv = p ? __ldg(&x[idx]) : make_float2(0.f, 0.f);
        int b = p ? buckets[idx] : 0;
        b = ((unsigned)b < NB) ? b : (NB - 1);
        int vat = b * VSTH;
        unsigned long long x0 = pack2(xv.x, xv.x);
        unsigned long long x1 = pack2(xv.y, xv.y);
        float a0 = sc[b], a1 = 0.f;

        #pragma unroll
        for (int jj = 0; jj < JJ; jj++) {
            unsigned long long a2  = *(const unsigned long long*)&sAB[2 * jj];
            unsigned long long b2w = *(const unsigned long long*)&sAB[HID + 2 * jj];
            unsigned long long c2  = *(const unsigned long long*)&sC[2 * jj];
            unsigned long long z = fma2(x1, b2w, c2);
            z = fma2(x0, a2, z);
            float z0, z1;
            unpack2(z, z0, z1);
            float h0 = fmaxf(z0, 0.f);
            float h1 = fmaxf(z1, 0.f);
            unsigned vh = sVh[vat + jj];
            float2 vf = __half22float2(*reinterpret_cast<__half2*>(&vh));
            a0 = fmaf(h0, vf.x, a0);
            a1 = fmaf(h1, vf.y, a1);
        }
        if (p) out[idx] = a0 + a1;
    }
}

extern "C" void kernel_launch(void* const* d_in, const int* in_sizes, int n_in,
                              void* d_out, int out_size) {
    const float2* x     = (const float2*)d_in[0];
    const int* buckets  = (const int*)d_in[1];
    const float* W1     = (const float*)d_in[2];
    const float* b1     = (const float*)d_in[3];
    const float* W2     = (const float*)d_in[4];
    const float* b2v    = (const float*)d_in[5];
    const float* Wh     = (const float*)d_in[6];
    const float* bh     = (const float*)d_in[7];
    float* out          = (float*)d_out;

    int B = in_sizes[1];  // buckets element count = row count

    lightwin_kernel<<<NBLK, TPB>>>(x, buckets, W1, b1, W2, b2v, Wh, bh, out, B);
}

// round 16
// speedup vs baseline: 2.2044x; 1.0667x over previous
#include <cuda_runtime.h>
#include <cuda_fp16.h>

#define NB    50
#define HID   32
#define HALFD 16
#define JJ    16         // HID/2 packed pairs
#define VSTH  17         // u32 stride per bucket row (odd -> <=2-way conflicts)
#define W2ST  17         // padded W2 row stride in smem
#define TPB   256
#define CR    4          // rows per thread (2 adjacent pairs)
#define CHROWS (TPB * CR)   // 1024 rows per chunk
#define NBLK  740        // 148 SMs x 5 blocks, persistent

__device__ __forceinline__ unsigned long long pack2(float lo, float hi) {
    unsigned long long r;
    asm("mov.b64 %0, {%1, %2};" : "=l"(r) : "f"(lo), "f"(hi));
    return r;
}
__device__ __forceinline__ unsigned long long fma2(unsigned long long a,
                                                   unsigned long long b,
                                                   unsigned long long c) {
    unsigned long long d;
    asm("fma.rn.f32x2 %0, %1, %2, %3;" : "=l"(d) : "l"(a), "l"(b), "l"(c));
    return d;
}
__device__ __forceinline__ void unpack2(unsigned long long v, float& lo, float& hi) {
    asm("mov.b64 {%0, %1}, %2;" : "=f"(lo), "=f"(hi) : "l"(v));
}

__global__ __launch_bounds__(TPB, 5)
void lightwin_kernel(const float4* __restrict__ x4, const int2* __restrict__ bk2,
                     const float* __restrict__ W1, const float* __restrict__ b1,
                     const float* __restrict__ W2, const float* __restrict__ b2v,
                     const float* __restrict__ Wh, const float* __restrict__ bh,
                     float2* __restrict__ out2, int B, int nchunks) {
    __shared__ __align__(16) float sAB[HID * 2];     // W1 row0 | W1 row1
    __shared__ __align__(16) float sC[HID];          // b1
    __shared__ unsigned sVh[NB * VSTH];              // V = Wh @ W2^T, half2 pairs
    __shared__ float sc[NB];                         // c[b] = bh[b] + b2 . Wh[b]
    // staging for fused precompute (coalesced loads; bank-aware strides)
    __shared__ float sW2[HID * W2ST];
    __shared__ float sWh[NB * HALFD];
    __shared__ float sB2[HALFD];
    __shared__ float sBh[NB];

    int tid = threadIdx.x;

    // ---- stage 1: coalesced global -> smem (once per persistent block)
    if (tid < HID * 2)     sAB[tid] = W1[tid];
    if (tid < HID)         sC[tid]  = b1[tid];
    for (int i = tid; i < HID * HALFD; i += TPB)
        sW2[(i >> 4) * W2ST + (i & 15)] = W2[i];
    for (int i = tid; i < NB * HALFD; i += TPB)
        sWh[i] = Wh[i];
    if (tid < HALFD)       sB2[tid] = b2v[tid];
    if (tid < NB)          sBh[tid] = bh[tid];
    __syncthreads();

    // ---- stage 2: combined head weights V (half2) + folded bias c
    for (int e = tid; e < NB * JJ; e += TPB) {
        int b = e >> 4, jj = e & 15;
        const float* whp = &sWh[b * HALFD];
        const float* wa  = &sW2[(2 * jj)     * W2ST];
        const float* wb  = &sW2[(2 * jj + 1) * W2ST];
        float s0 = 0.f, s1 = 0.f;
        #pragma unroll
        for (int k = 0; k < HALFD; k++) {
            float wh = whp[k];
            s0 = fmaf(wa[k], wh, s0);
            s1 = fmaf(wb[k], wh, s1);
        }
        __half2 h = __floats2half2_rn(s0, s1);
        sVh[b * VSTH + jj] = *reinterpret_cast<unsigned*>(&h);
    }
    for (int b = tid; b < NB; b += TPB) {
        float s = sBh[b];
        #pragma unroll
        for (int k = 0; k < HALFD; k++)
            s = fmaf(sB2[k], sWh[b * HALFD + k], s);
        sc[b] = s;
    }
    __syncthreads();

    int halfB = B >> 1;   // number of complete row-pairs

    // ---- stage 3: persistent block-stride loop over 1024-row chunks (R10 schedule)
    for (int ch = blockIdx.x; ch < nchunks; ch += NBLK) {
        // thread t handles row pairs: chunk*512 + t (pass 0), +256 (pass 1)
        int pbase = ch * (CHROWS / 2) + tid;   // pair index, pass 0

        unsigned long long x0d[CR], x1d[CR];
        float acc0[CR], acc1[CR];
        int   va[CR];
        bool  pv[2];

        #pragma unroll
        for (int p = 0; p < 2; p++) {
            int pidx = pbase + p * TPB;
            bool v = pidx < halfB;
            pv[p] = v;
            float4 xv = v ? __ldg(&x4[pidx]) : make_float4(0.f, 0.f, 0.f, 0.f);
            int2  bb = v ? __ldg(&bk2[pidx]) : make_int2(0, 0);
            int b0 = ((unsigned)bb.x < NB) ? bb.x : (NB - 1);
            int b1i = ((unsigned)bb.y < NB) ? bb.y : (NB - 1);
            va[2 * p]     = b0  * VSTH;
            va[2 * p + 1] = b1i * VSTH;
            x0d[2 * p]     = pack2(xv.x, xv.x);
            x1d[2 * p]     = pack2(xv.y, xv.y);
            x0d[2 * p + 1] = pack2(xv.z, xv.z);
            x1d[2 * p + 1] = pack2(xv.w, xv.w);
            acc0[2 * p]     = sc[b0];     // head bias folded into accumulator
            acc0[2 * p + 1] = sc[b1i];
            acc1[2 * p]     = 0.f;
            acc1[2 * p + 1] = 0.f;
        }

        #pragma unroll
        for (int jp = 0; jp < JJ / 2; jp++) {
            // warp-uniform weights: 3x LDS.128 per 2 jj (u64 views fold to renames)
            float4 a4 = *(const float4*)&sAB[4 * jp];
            float4 b4 = *(const float4*)&sAB[HID + 4 * jp];
            float4 c4 = *(const float4*)&sC[4 * jp];
            unsigned long long a2_0 = pack2(a4.x, a4.y), a2_1 = pack2(a4.z, a4.w);
            unsigned long long w2_0 = pack2(b4.x, b4.y), w2_1 = pack2(b4.z, b4.w);
            unsigned long long c2_0 = pack2(c4.x, c4.y), c2_1 = pack2(c4.z, c4.w);
            #pragma unroll
            for (int r = 0; r < CR; r++) {
                // jj = 2*jp
                {
                    unsigned long long z = fma2(x1d[r], w2_0, c2_0);
                    z = fma2(x0d[r], a2_0, z);
                    float z0, z1;
                    unpack2(z, z0, z1);
                    float h0 = fmaxf(z0, 0.f);
                    float h1 = fmaxf(z1, 0.f);
                    unsigned vh = sVh[va[r] + 2 * jp];
                    float2 vf = __half22float2(*reinterpret_cast<__half2*>(&vh));
                    acc0[r] = fmaf(h0, vf.x, acc0[r]);
                    acc1[r] = fmaf(h1, vf.y, acc1[r]);
                }
                // jj = 2*jp + 1
                {
                    unsigned long long z = fma2(x1d[r], w2_1, c2_1);
                    z = fma2(x0d[r], a2_1, z);
                    float z0, z1;
                    unpack2(z, z0, z1);
                    float h0 = fmaxf(z0, 0.f);
                    float h1 = fmaxf(z1, 0.f);
                    unsigned vh = sVh[va[r] + 2 * jp + 1];
                    float2 vf = __half22float2(*reinterpret_cast<__half2*>(&vh));
                    acc0[r] = fmaf(h0, vf.x, acc0[r]);
                    acc1[r] = fmaf(h1, vf.y, acc1[r]);
                }
            }
        }

        #pragma unroll
        for (int p = 0; p < 2; p++) {
            int pidx = pbase + p * TPB;
            if (pv[p]) {
                float2 o;
                o.x = acc0[2 * p]     + acc1[2 * p];
                o.y = acc0[2 * p + 1] + acc1[2 * p + 1];
                out2[pidx] = o;
            }
        }
    }
}

extern "C" void kernel_launch(void* const* d_in, const int* in_sizes, int n_in,
                              void* d_out, int out_size) {
    const float4* x4    = (const float4*)d_in[0];   // 2 rows of float2 per float4
    const int2* bk2     = (const int2*)d_in[1];     // 2 buckets per int2
    const float* W1     = (const float*)d_in[2];
    const float* b1     = (const float*)d_in[3];
    const float* W2     = (const float*)d_in[4];
    const float* b2v    = (const float*)d_in[5];
    const float* Wh     = (const float*)d_in[6];
    const float* bh     = (const float*)d_in[7];
    float2* out2        = (float2*)d_out;

    int B = in_sizes[1];  // buckets element count = row count (even)

    int nchunks = (B + CHROWS - 1) / CHROWS;   // 1954
    int grid = NBLK < nchunks ? NBLK : nchunks;
    lightwin_kernel<<<grid, TPB>>>(x4, bk2, W1, b1, W2, b2v, Wh, bh, out2, B, nchunks);
}

// round 17
// speedup vs baseline: 2.2410x; 1.0166x over previous
#include <cuda_runtime.h>
#include <cuda_fp16.h>

#define NB    50
#define HID   32
#define HALFD 16
#define JJ    16         // HID/2 packed pairs
#define VSTH  17         // u32 stride per bucket row (odd -> <=2-way conflicts)
#define W2ST  17         // padded W2 row stride in smem
#define TPB   256
#define CR    4          // rows per thread (2 adjacent pairs)
#define CHROWS (TPB * CR)   // 1024 rows per chunk
#define NBLK  740        // 148 SMs x 5 blocks, persistent

__device__ __forceinline__ unsigned long long pack2(float lo, float hi) {
    unsigned long long r;
    asm("mov.b64 %0, {%1, %2};" : "=l"(r) : "f"(lo), "f"(hi));
    return r;
}
__device__ __forceinline__ unsigned long long fma2(unsigned long long a,
                                                   unsigned long long b,
                                                   unsigned long long c) {
    unsigned long long d;
    asm("fma.rn.f32x2 %0, %1, %2, %3;" : "=l"(d) : "l"(a), "l"(b), "l"(c));
    return d;
}
__device__ __forceinline__ void unpack2(unsigned long long v, float& lo, float& hi) {
    asm("mov.b64 {%0, %1}, %2;" : "=f"(lo), "=f"(hi) : "l"(v));
}

__global__ __launch_bounds__(TPB, 5)
void lightwin_kernel(const float4* __restrict__ x4, const int2* __restrict__ bk2,
                     const float* __restrict__ W1, const float* __restrict__ b1,
                     const float* __restrict__ W2, const float* __restrict__ b2v,
                     const float* __restrict__ Wh, const float* __restrict__ bh,
                     float2* __restrict__ out2, int B, int nchunks) {
    __shared__ __align__(16) float sAB[HID * 2];     // W1 row0 | W1 row1
    __shared__ __align__(16) float sC[HID];          // b1
    __shared__ unsigned sVh[NB * VSTH];              // V = Wh @ W2^T, half2 pairs
    __shared__ float sc[NB];                         // c[b] = bh[b] + b2 . Wh[b]
    __shared__ float sW2[HID * W2ST];
    __shared__ float sWh[NB * HALFD];
    __shared__ float sB2[HALFD];
    __shared__ float sBh[NB];

    int tid = threadIdx.x;
    int halfB = B >> 1;

    // ---- entry: L2-prefetch this block's first chunk (overlaps precompute)
    {
        int pb0 = blockIdx.x * (CHROWS / 2) + tid;
        if (pb0 < halfB) {
            asm volatile("prefetch.global.L2 [%0];" :: "l"(x4 + pb0));
            asm volatile("prefetch.global.L2 [%0];" :: "l"(bk2 + pb0));
        }
        int pb1 = pb0 + TPB;
        if (pb1 < halfB) {
            asm volatile("prefetch.global.L2 [%0];" :: "l"(x4 + pb1));
            asm volatile("prefetch.global.L2 [%0];" :: "l"(bk2 + pb1));
        }
    }

    // ---- stage 1: coalesced global -> smem (once per persistent block)
    if (tid < HID * 2)     sAB[tid] = W1[tid];
    if (tid < HID)         sC[tid]  = b1[tid];
    for (int i = tid; i < HID * HALFD; i += TPB)
        sW2[(i >> 4) * W2ST + (i & 15)] = W2[i];
    for (int i = tid; i < NB * HALFD; i += TPB)
        sWh[i] = Wh[i];
    if (tid < HALFD)       sB2[tid] = b2v[tid];
    if (tid < NB)          sBh[tid] = bh[tid];
    __syncthreads();

    // ---- stage 2: combined head weights V (half2) + folded bias c
    for (int e = tid; e < NB * JJ; e += TPB) {
        int b = e >> 4, jj = e & 15;
        const float* whp = &sWh[b * HALFD];
        const float* wa  = &sW2[(2 * jj)     * W2ST];
        const float* wb  = &sW2[(2 * jj + 1) * W2ST];
        float s0 = 0.f, s1 = 0.f;
        #pragma unroll
        for (int k = 0; k < HALFD; k++) {
            float wh = whp[k];
            s0 = fmaf(wa[k], wh, s0);
            s1 = fmaf(wb[k], wh, s1);
        }
        __half2 h = __floats2half2_rn(s0, s1);
        sVh[b * VSTH + jj] = *reinterpret_cast<unsigned*>(&h);
    }
    for (int b = tid; b < NB; b += TPB) {
        float s = sBh[b];
        #pragma unroll
        for (int k = 0; k < HALFD; k++)
            s = fmaf(sB2[k], sWh[b * HALFD + k], s);
        sc[b] = s;
    }
    __syncthreads();

    // ---- stage 3: persistent block-stride loop over 1024-row chunks
    for (int ch = blockIdx.x; ch < nchunks; ch += NBLK) {
        int pbase = ch * (CHROWS / 2) + tid;   // pair index, pass 0

        unsigned long long x0d[CR], x1d[CR];
        float acc0[CR], acc1[CR];
        int   va[CR];

        #pragma unroll
        for (int p = 0; p < 2; p++) {
            int pidx = pbase + p * TPB;
            bool v = pidx < halfB;
            float4 xv = v ? __ldg(&x4[pidx]) : make_float4(0.f, 0.f, 0.f, 0.f);
            int2  bb = v ? __ldg(&bk2[pidx]) : make_int2(0, 0);
            int b0  = ((unsigned)bb.x < NB) ? bb.x : (NB - 1);
            int b1i = ((unsigned)bb.y < NB) ? bb.y : (NB - 1);
            va[2 * p]     = b0  * VSTH;
            va[2 * p + 1] = b1i * VSTH;
            x0d[2 * p]     = pack2(xv.x, xv.x);
            x1d[2 * p]     = pack2(xv.y, xv.y);
            x0d[2 * p + 1] = pack2(xv.z, xv.z);
            x1d[2 * p + 1] = pack2(xv.w, xv.w);
            acc0[2 * p]     = sc[b0];     // head bias folded in
            acc0[2 * p + 1] = sc[b1i];
            acc1[2 * p]     = 0.f;
            acc1[2 * p + 1] = 0.f;
        }

        // gather prefetch, distance 1: vh for jj arrives a full r-loop early
        unsigned vh[CR];
        #pragma unroll
        for (int r = 0; r < CR; r++) vh[r] = sVh[va[r]];

        #pragma unroll
        for (int jj = 0; jj < JJ; jj++) {
            // warp-uniform weight pairs: broadcast LDS.64
            unsigned long long a2  = *(const unsigned long long*)&sAB[2 * jj];
            unsigned long long b2w = *(const unsigned long long*)&sAB[HID + 2 * jj];
            unsigned long long c2  = *(const unsigned long long*)&sC[2 * jj];

            unsigned vhn[CR];
            if (jj < JJ - 1) {
                #pragma unroll
                for (int r = 0; r < CR; r++) vhn[r] = sVh[va[r] + jj + 1];
            }

            #pragma unroll
            for (int r = 0; r < CR; r++) {
                unsigned long long z = fma2(x1d[r], b2w, c2);
                z = fma2(x0d[r], a2, z);
                float z0, z1;
                unpack2(z, z0, z1);
                float h0 = fmaxf(z0, 0.f);
                float h1 = fmaxf(z1, 0.f);
                unsigned vcur = vh[r];
                float2 vf = __half22float2(*reinterpret_cast<__half2*>(&vcur));
                acc0[r] = fmaf(h0, vf.x, acc0[r]);
                acc1[r] = fmaf(h1, vf.y, acc1[r]);
            }

            if (jj < JJ - 1) {
                #pragma unroll
                for (int r = 0; r < CR; r++) vh[r] = vhn[r];
            }
        }

        #pragma unroll
        for (int p = 0; p < 2; p++) {
            int pidx = pbase + p * TPB;
            if (pidx < halfB) {
                float2 o;
                o.x = acc0[2 * p]     + acc1[2 * p];
                o.y = acc0[2 * p + 1] + acc1[2 * p + 1];
                out2[pidx] = o;
            }
        }
    }
}

extern "C" void kernel_launch(void* const* d_in, const int* in_sizes, int n_in,
                              void* d_out, int out_size) {
    const float4* x4    = (const float4*)d_in[0];   // 2 rows of float2 per float4
    const int2* bk2     = (const int2*)d_in[1];     // 2 buckets per int2
    const float* W1     = (const float*)d_in[2];
    const float* b1     = (const float*)d_in[3];
    const float* W2     = (const float*)d_in[4];
    const float* b2v    = (const float*)d_in[5];
    const float* Wh     = (const float*)d_in[6];
    const float* bh     = (const float*)d_in[7];
    float2* out2        = (float2*)d_out;

    int B = in_sizes[1];  // buckets element count = row count (even)

    int nchunks = (B + CHROWS - 1) / CHROWS;   // 1954
    int grid = NBLK < nchunks ? NBLK : nchunks;
    lightwin_kernel<<<grid, TPB>>>(x4, bk2, W1, b1, W2, b2v, Wh, bh, out2, B, nchunks);
}